// round 1
// baseline (speedup 1.0000x reference)
#include <cuda_runtime.h>

#define NN 100000
#define NE 3200000
#define IND 128
#define HD 64
#define OD 10
#define NG 64

// ---- device scratch (no allocs allowed) ----
__device__ int   g_deg[NN];
__device__ int   g_cur[NN];
__device__ int   g_rs[NN + 1];
__device__ int   g_part[512];
__device__ int   g_ecol[NE];
__device__ float g_eval[NE];
__device__ float g_H [NN * HD];
__device__ float g_A1[NN * HD];
__device__ float g_A2[NN * HD];
__device__ float g_A3[NN * HD];
__device__ float g_sum[NG * HD];
__device__ int   g_cnt[NG];

__global__ void k_zero() {
    int i  = blockIdx.x * blockDim.x + threadIdx.x;
    int st = gridDim.x * blockDim.x;
    for (int j = i; j < NN; j += st) { g_deg[j] = 0; g_cur[j] = 0; }
    for (int j = i; j < NG * HD; j += st) g_sum[j] = 0.f;
    for (int j = i; j < NG; j += st) g_cnt[j] = 0;
}

__global__ void k_hist(const int* __restrict__ rows) {
    int i = blockIdx.x * blockDim.x + threadIdx.x;
    if (i < NE) atomicAdd(&g_deg[rows[i]], 1);
}

__global__ void k_scan1() {
    __shared__ int s[256];
    int i = blockIdx.x * 256 + threadIdx.x;
    int v = (i < NN) ? g_deg[i] : 0;
    s[threadIdx.x] = v;
    __syncthreads();
    for (int o = 128; o > 0; o >>= 1) {
        if (threadIdx.x < o) s[threadIdx.x] += s[threadIdx.x + o];
        __syncthreads();
    }
    if (threadIdx.x == 0) g_part[blockIdx.x] = s[0];
}

__global__ void k_scan2(int nb) {
    __shared__ int s[512];
    int t = threadIdx.x;
    int v = (t < nb) ? g_part[t] : 0;
    s[t] = v;
    __syncthreads();
    for (int o = 1; o < 512; o <<= 1) {
        int x = 0;
        if (t >= o) x = s[t - o];
        __syncthreads();
        if (t >= o) s[t] += x;
        __syncthreads();
    }
    if (t < nb) g_part[t] = s[t] - v;  // exclusive
}

__global__ void k_scan3() {
    __shared__ int s[256];
    int t = threadIdx.x;
    int i = blockIdx.x * 256 + t;
    int v = (i < NN) ? g_deg[i] : 0;
    s[t] = v;
    __syncthreads();
    for (int o = 1; o < 256; o <<= 1) {
        int x = 0;
        if (t >= o) x = s[t - o];
        __syncthreads();
        if (t >= o) s[t] += x;
        __syncthreads();
    }
    if (i < NN) g_rs[i] = g_part[blockIdx.x] + s[t] - v;
    if (i == NN - 1) g_rs[NN] = g_part[blockIdx.x] + s[t];
}

__global__ void k_scatter(const int* __restrict__ rows, const int* __restrict__ cols,
                          const float* __restrict__ vals) {
    int i = blockIdx.x * blockDim.x + threadIdx.x;
    if (i < NE) {
        int r = rows[i];
        int p = g_rs[r] + atomicAdd(&g_cur[r], 1);
        g_ecol[p] = cols[i];
        g_eval[p] = vals[i];
    }
}

// H[m][j] = sum_k A[m][k] * W[j][k] + b[j]   (A: [NN,K], W: [64,K])
template <int K>
__global__ void __launch_bounds__(128) k_gemm(const float* __restrict__ A,
                                              const float* __restrict__ W,
                                              const float* __restrict__ b,
                                              float* __restrict__ O) {
    __shared__ float Ws[K][HD];      // transposed: Ws[k][j]
    __shared__ float Xs[128][17];    // 16-k chunk, padded
    int t = threadIdx.x;

    // load W transposed (conflict-free smem stores; j contiguous across lanes)
    for (int f = t; f < HD * (K / 4); f += 128) {
        int k4 = f / HD, j = f - k4 * HD;
        const float4 w = *(const float4*)(W + j * K + k4 * 4);
        Ws[k4 * 4 + 0][j] = w.x;
        Ws[k4 * 4 + 1][j] = w.y;
        Ws[k4 * 4 + 2][j] = w.z;
        Ws[k4 * 4 + 3][j] = w.w;
    }

    float acc[HD];
#pragma unroll
    for (int j = 0; j < HD; j++) acc[j] = 0.f;

    int mb = blockIdx.x * 128;
    int node = mb + t;

    for (int k0 = 0; k0 < K; k0 += 16) {
        __syncthreads();
        for (int f = t; f < 128 * 16; f += 128) {
            int mm = f >> 4, kk = f & 15;
            int n2 = mb + mm;
            Xs[mm][kk] = (n2 < NN) ? A[n2 * K + k0 + kk] : 0.f;
        }
        __syncthreads();
#pragma unroll
        for (int kk = 0; kk < 16; kk++) {
            float x = Xs[t][kk];
#pragma unroll
            for (int j = 0; j < HD; j += 4) {
                float4 w = *(const float4*)&Ws[k0 + kk][j];
                acc[j]     += x * w.x;
                acc[j + 1] += x * w.y;
                acc[j + 2] += x * w.z;
                acc[j + 3] += x * w.w;
            }
        }
    }

    if (node < NN) {
#pragma unroll
        for (int j = 0; j < HD; j += 4) {
            float4 o;
            o.x = acc[j]     + b[j];
            o.y = acc[j + 1] + b[j + 1];
            o.z = acc[j + 2] + b[j + 2];
            o.w = acc[j + 3] + b[j + 3];
            *(float4*)(O + node * HD + j) = o;
        }
    }
}

// warp-per-row CSR SpMM + relu; lane owns 2 contiguous dims (float2)
__global__ void k_spmm(const float* __restrict__ Hin, float* __restrict__ Ho) {
    int w    = (blockIdx.x * blockDim.x + threadIdx.x) >> 5;
    int lane = threadIdx.x & 31;
    if (w >= NN) return;
    int s = g_rs[w], e = g_rs[w + 1];
    float ax = 0.f, ay = 0.f;
    int j = s;
    for (; j + 4 <= e; j += 4) {
        int   c0 = g_ecol[j], c1 = g_ecol[j + 1], c2 = g_ecol[j + 2], c3 = g_ecol[j + 3];
        float v0 = g_eval[j], v1 = g_eval[j + 1], v2 = g_eval[j + 2], v3 = g_eval[j + 3];
        float2 h0 = *(const float2*)(Hin + c0 * HD + lane * 2);
        float2 h1 = *(const float2*)(Hin + c1 * HD + lane * 2);
        float2 h2 = *(const float2*)(Hin + c2 * HD + lane * 2);
        float2 h3 = *(const float2*)(Hin + c3 * HD + lane * 2);
        ax += v0 * h0.x; ay += v0 * h0.y;
        ax += v1 * h1.x; ay += v1 * h1.y;
        ax += v2 * h2.x; ay += v2 * h2.y;
        ax += v3 * h3.x; ay += v3 * h3.y;
    }
    for (; j < e; j++) {
        int c = g_ecol[j];
        float v = g_eval[j];
        float2 h = *(const float2*)(Hin + c * HD + lane * 2);
        ax += v * h.x; ay += v * h.y;
    }
    float2 o;
    o.x = fmaxf(ax, 0.f);
    o.y = fmaxf(ay, 0.f);
    *(float2*)(Ho + w * HD + lane * 2) = o;
}

__global__ void k_pool(const int* __restrict__ batch) {
    __shared__ float ss[NG * HD];
    __shared__ int   sc[NG];
    for (int i = threadIdx.x; i < NG * HD; i += blockDim.x) ss[i] = 0.f;
    for (int i = threadIdx.x; i < NG; i += blockDim.x) sc[i] = 0;
    __syncthreads();
    int tid = blockIdx.x * blockDim.x + threadIdx.x;
    int st  = gridDim.x * blockDim.x;
    const float inv3 = 1.0f / 3.0f;
    for (int f = tid; f < NN * HD; f += st) {
        int node = f >> 6;
        int d    = f & 63;
        int g    = batch[node];
        float v  = (g_A1[f] + g_A2[f] + g_A3[f]) * inv3;
        atomicAdd(&ss[g * HD + d], v);
    }
    for (int n = tid; n < NN; n += st) atomicAdd(&sc[batch[n]], 1);
    __syncthreads();
    for (int i = threadIdx.x; i < NG * HD; i += blockDim.x)
        if (ss[i] != 0.f) atomicAdd(&g_sum[i], ss[i]);
    for (int i = threadIdx.x; i < NG; i += blockDim.x)
        if (sc[i] != 0) atomicAdd(&g_cnt[i], sc[i]);
}

__global__ void k_final(const float* __restrict__ Wout, const float* __restrict__ bout,
                        float* __restrict__ out) {
    int g = threadIdx.x;
    if (g >= NG) return;
    float cnt = fmaxf((float)g_cnt[g], 1.0f);
    float inv = 1.0f / cnt;
    float p[HD];
#pragma unroll
    for (int d = 0; d < HD; d++) p[d] = g_sum[g * HD + d] * inv;
    float lg[OD];
    float mx = -1e30f;
#pragma unroll
    for (int j = 0; j < OD; j++) {
        float a = bout[j];
#pragma unroll
        for (int d = 0; d < HD; d++) a += p[d] * Wout[j * HD + d];
        lg[j] = a;
        mx = fmaxf(mx, a);
    }
    float sum = 0.f;
#pragma unroll
    for (int j = 0; j < OD; j++) { lg[j] = expf(lg[j] - mx); sum += lg[j]; }
    float is = 1.0f / sum;
#pragma unroll
    for (int j = 0; j < OD; j++) out[g * OD + j] = lg[j] * is;
}

extern "C" void kernel_launch(void* const* d_in, const int* in_sizes, int n_in,
                              void* d_out, int out_size) {
    const float* X    = (const float*)d_in[0];
    const float* vals = (const float*)d_in[1];
    const float* W1   = (const float*)d_in[2];
    const float* b1   = (const float*)d_in[3];
    const float* W2   = (const float*)d_in[4];
    const float* b2   = (const float*)d_in[5];
    const float* W3   = (const float*)d_in[6];
    const float* b3   = (const float*)d_in[7];
    const float* Wo   = (const float*)d_in[8];
    const float* bo   = (const float*)d_in[9];
    const int*   rows = (const int*)d_in[10];
    const int*   cols = (const int*)d_in[11];
    const int*   batc = (const int*)d_in[12];
    float* out = (float*)d_out;

    float *pH, *pA1, *pA2, *pA3;
    cudaGetSymbolAddress((void**)&pH,  g_H);
    cudaGetSymbolAddress((void**)&pA1, g_A1);
    cudaGetSymbolAddress((void**)&pA2, g_A2);
    cudaGetSymbolAddress((void**)&pA3, g_A3);

    const int NB = (NN + 255) / 256;          // 391
    const int EB = (NE + 255) / 256;          // 12500
    const int GB = (NN + 127) / 128;          // 782 gemm blocks
    const int SB = (NN * 32 + 255) / 256;     // 12500 spmm blocks (warp/row)

    // CSR build (per call, deterministic)
    k_zero<<<256, 256>>>();
    k_hist<<<EB, 256>>>(rows);
    k_scan1<<<NB, 256>>>();
    k_scan2<<<1, 512>>>(NB);
    k_scan3<<<NB, 256>>>();
    k_scatter<<<EB, 256>>>(rows, cols, vals);

    // layer 1
    k_gemm<IND><<<GB, 128>>>(X, W1, b1, pH);
    k_spmm<<<SB, 256>>>(pH, pA1);
    // layer 2
    k_gemm<HD><<<GB, 128>>>(pA1, W2, b2, pH);
    k_spmm<<<SB, 256>>>(pH, pA2);
    // layer 3
    k_gemm<HD><<<GB, 128>>>(pA2, W3, b3, pH);
    k_spmm<<<SB, 256>>>(pH, pA3);

    // pool + head
    k_pool<<<512, 256>>>(batc);
    k_final<<<1, 64>>>(Wo, bo, out);
}

// round 2
// speedup vs baseline: 1.0701x; 1.0701x over previous
#include <cuda_runtime.h>
#include <cuda_fp16.h>

#define NN 100000
#define NE 3200000
#define IND 128
#define HD 64
#define OD 10
#define NG 64

// ---- device scratch (no allocs allowed) ----
__device__ int    g_deg[NN];
__device__ int    g_cur[NN];
__device__ int    g_rs[NN + 1];
__device__ int    g_part[512];
__device__ int2   g_edge[NE];             // (col, val bits)
__device__ __half g_Hh[NN * HD];          // fp16 GEMM output (SpMM input)
__device__ float  g_A1[NN * HD];
__device__ float  g_A2[NN * HD];
__device__ float  g_A3[NN * HD];
__device__ float  g_sum[NG * HD];
__device__ int    g_cnt[NG];

__global__ void k_zero() {
    int i  = blockIdx.x * blockDim.x + threadIdx.x;
    int st = gridDim.x * blockDim.x;
    for (int j = i; j < NN; j += st) { g_deg[j] = 0; g_cur[j] = 0; }
    for (int j = i; j < NG * HD; j += st) g_sum[j] = 0.f;
    for (int j = i; j < NG; j += st) g_cnt[j] = 0;
}

__global__ void k_hist(const int* __restrict__ rows) {
    int i = blockIdx.x * blockDim.x + threadIdx.x;
    if (i < NE) atomicAdd(&g_deg[rows[i]], 1);
}

__global__ void k_scan1() {
    __shared__ int s[256];
    int i = blockIdx.x * 256 + threadIdx.x;
    int v = (i < NN) ? g_deg[i] : 0;
    s[threadIdx.x] = v;
    __syncthreads();
    for (int o = 128; o > 0; o >>= 1) {
        if (threadIdx.x < o) s[threadIdx.x] += s[threadIdx.x + o];
        __syncthreads();
    }
    if (threadIdx.x == 0) g_part[blockIdx.x] = s[0];
}

__global__ void k_scan2(int nb) {
    __shared__ int s[512];
    int t = threadIdx.x;
    int v = (t < nb) ? g_part[t] : 0;
    s[t] = v;
    __syncthreads();
    for (int o = 1; o < 512; o <<= 1) {
        int x = 0;
        if (t >= o) x = s[t - o];
        __syncthreads();
        if (t >= o) s[t] += x;
        __syncthreads();
    }
    if (t < nb) g_part[t] = s[t] - v;  // exclusive
}

__global__ void k_scan3() {
    __shared__ int s[256];
    int t = threadIdx.x;
    int i = blockIdx.x * 256 + t;
    int v = (i < NN) ? g_deg[i] : 0;
    s[t] = v;
    __syncthreads();
    for (int o = 1; o < 256; o <<= 1) {
        int x = 0;
        if (t >= o) x = s[t - o];
        __syncthreads();
        if (t >= o) s[t] += x;
        __syncthreads();
    }
    if (i < NN) g_rs[i] = g_part[blockIdx.x] + s[t] - v;
    if (i == NN - 1) g_rs[NN] = g_part[blockIdx.x] + s[t];
}

__global__ void k_scatter(const int* __restrict__ rows, const int* __restrict__ cols,
                          const float* __restrict__ vals) {
    int i = blockIdx.x * blockDim.x + threadIdx.x;
    if (i < NE) {
        int r = rows[i];
        int p = g_rs[r] + atomicAdd(&g_cur[r], 1);
        g_edge[p] = make_int2(cols[i], __float_as_int(vals[i]));
    }
}

// H[m][j] = sum_k A[m][k] * W[j][k] + b[j]   (A: [NN,K], W: [64,K]) -> fp16 out
// Uses packed fma.rn.f32x2 (FFMA2) for 2x fp32 MAC throughput.
template <int K>
__global__ void __launch_bounds__(128) k_gemm(const float* __restrict__ A,
                                              const float* __restrict__ W,
                                              const float* __restrict__ b,
                                              __half* __restrict__ O) {
    __shared__ __align__(16) float Ws[K][HD];  // transposed: Ws[k][j]
    __shared__ float Xs[128][17];              // 16-k chunk, padded
    int t = threadIdx.x;

    // load W transposed
    for (int f = t; f < HD * (K / 4); f += 128) {
        int k4 = f / HD, j = f - k4 * HD;
        const float4 w = *(const float4*)(W + j * K + k4 * 4);
        Ws[k4 * 4 + 0][j] = w.x;
        Ws[k4 * 4 + 1][j] = w.y;
        Ws[k4 * 4 + 2][j] = w.z;
        Ws[k4 * 4 + 3][j] = w.w;
    }

    unsigned long long acc[HD / 2];
#pragma unroll
    for (int j = 0; j < HD / 2; j++) acc[j] = 0ULL;

    int mb = blockIdx.x * 128;
    int node = mb + t;

    for (int k0 = 0; k0 < K; k0 += 16) {
        __syncthreads();
        for (int f = t; f < 128 * 16; f += 128) {
            int mm = f >> 4, kk = f & 15;
            int n2 = mb + mm;
            Xs[mm][kk] = (n2 < NN) ? A[n2 * K + k0 + kk] : 0.f;
        }
        __syncthreads();
#pragma unroll
        for (int kk = 0; kk < 16; kk++) {
            float x = Xs[t][kk];
            unsigned long long xx;
            asm("mov.b64 %0, {%1, %1};" : "=l"(xx) : "f"(x));
#pragma unroll
            for (int j = 0; j < HD; j += 4) {
                const ulonglong2 w = *(const ulonglong2*)&Ws[k0 + kk][j];
                asm("fma.rn.f32x2 %0, %1, %2, %0;" : "+l"(acc[j / 2])     : "l"(w.x), "l"(xx));
                asm("fma.rn.f32x2 %0, %1, %2, %0;" : "+l"(acc[j / 2 + 1]) : "l"(w.y), "l"(xx));
            }
        }
    }

    if (node < NN) {
#pragma unroll
        for (int j = 0; j < HD; j += 8) {
            uint4 st;
            unsigned* sp = (unsigned*)&st;
#pragma unroll
            for (int p = 0; p < 4; p++) {
                float lo, hi;
                asm("mov.b64 {%0, %1}, %2;" : "=f"(lo), "=f"(hi) : "l"(acc[j / 2 + p]));
                __half2 h2 = __floats2half2_rn(lo + b[j + 2 * p], hi + b[j + 2 * p + 1]);
                sp[p] = *(unsigned*)&h2;
            }
            *(uint4*)(O + node * HD + j) = st;
        }
    }
}

// warp-per-row CSR SpMM + relu; lane owns 2 contiguous dims (half2 gather)
__global__ void k_spmm(const __half* __restrict__ Hin, float* __restrict__ Ho) {
    int w    = (blockIdx.x * blockDim.x + threadIdx.x) >> 5;
    int lane = threadIdx.x & 31;
    if (w >= NN) return;
    int s = g_rs[w], e = g_rs[w + 1];
    float ax = 0.f, ay = 0.f;
    int j = s;
    for (; j + 4 <= e; j += 4) {
        int2 e0 = g_edge[j], e1 = g_edge[j + 1], e2 = g_edge[j + 2], e3 = g_edge[j + 3];
        __half2 h0 = *(const __half2*)(Hin + e0.x * HD + lane * 2);
        __half2 h1 = *(const __half2*)(Hin + e1.x * HD + lane * 2);
        __half2 h2 = *(const __half2*)(Hin + e2.x * HD + lane * 2);
        __half2 h3 = *(const __half2*)(Hin + e3.x * HD + lane * 2);
        float2 f0 = __half22float2(h0);
        float2 f1 = __half22float2(h1);
        float2 f2 = __half22float2(h2);
        float2 f3 = __half22float2(h3);
        float v0 = __int_as_float(e0.y), v1 = __int_as_float(e1.y);
        float v2 = __int_as_float(e2.y), v3 = __int_as_float(e3.y);
        ax += v0 * f0.x; ay += v0 * f0.y;
        ax += v1 * f1.x; ay += v1 * f1.y;
        ax += v2 * f2.x; ay += v2 * f2.y;
        ax += v3 * f3.x; ay += v3 * f3.y;
    }
    for (; j < e; j++) {
        int2 ed = g_edge[j];
        float v = __int_as_float(ed.y);
        float2 f = __half22float2(*(const __half2*)(Hin + ed.x * HD + lane * 2));
        ax += v * f.x; ay += v * f.y;
    }
    float2 o;
    o.x = fmaxf(ax, 0.f);
    o.y = fmaxf(ay, 0.f);
    *(float2*)(Ho + w * HD + lane * 2) = o;
}

__global__ void k_pool(const int* __restrict__ batch) {
    __shared__ float ss[NG * HD];
    __shared__ int   sc[NG];
    for (int i = threadIdx.x; i < NG * HD; i += blockDim.x) ss[i] = 0.f;
    for (int i = threadIdx.x; i < NG; i += blockDim.x) sc[i] = 0;
    __syncthreads();
    int tid = blockIdx.x * blockDim.x + threadIdx.x;
    int st  = gridDim.x * blockDim.x;
    const float inv3 = 1.0f / 3.0f;
    for (int f = tid; f < NN * HD; f += st) {
        int node = f >> 6;
        int d    = f & 63;
        int g    = batch[node];
        float v  = (g_A1[f] + g_A2[f] + g_A3[f]) * inv3;
        atomicAdd(&ss[g * HD + d], v);
    }
    for (int n = tid; n < NN; n += st) atomicAdd(&sc[batch[n]], 1);
    __syncthreads();
    for (int i = threadIdx.x; i < NG * HD; i += blockDim.x)
        if (ss[i] != 0.f) atomicAdd(&g_sum[i], ss[i]);
    for (int i = threadIdx.x; i < NG; i += blockDim.x)
        if (sc[i] != 0) atomicAdd(&g_cnt[i], sc[i]);
}

__global__ void k_final(const float* __restrict__ Wout, const float* __restrict__ bout,
                        float* __restrict__ out) {
    int g = threadIdx.x;
    if (g >= NG) return;
    float cnt = fmaxf((float)g_cnt[g], 1.0f);
    float inv = 1.0f / cnt;
    float p[HD];
#pragma unroll
    for (int d = 0; d < HD; d++) p[d] = g_sum[g * HD + d] * inv;
    float lg[OD];
    float mx = -1e30f;
#pragma unroll
    for (int j = 0; j < OD; j++) {
        float a = bout[j];
#pragma unroll
        for (int d = 0; d < HD; d++) a += p[d] * Wout[j * HD + d];
        lg[j] = a;
        mx = fmaxf(mx, a);
    }
    float sum = 0.f;
#pragma unroll
    for (int j = 0; j < OD; j++) { lg[j] = expf(lg[j] - mx); sum += lg[j]; }
    float is = 1.0f / sum;
#pragma unroll
    for (int j = 0; j < OD; j++) out[g * OD + j] = lg[j] * is;
}

extern "C" void kernel_launch(void* const* d_in, const int* in_sizes, int n_in,
                              void* d_out, int out_size) {
    const float* X    = (const float*)d_in[0];
    const float* vals = (const float*)d_in[1];
    const float* W1   = (const float*)d_in[2];
    const float* b1   = (const float*)d_in[3];
    const float* W2   = (const float*)d_in[4];
    const float* b2   = (const float*)d_in[5];
    const float* W3   = (const float*)d_in[6];
    const float* b3   = (const float*)d_in[7];
    const float* Wo   = (const float*)d_in[8];
    const float* bo   = (const float*)d_in[9];
    const int*   rows = (const int*)d_in[10];
    const int*   cols = (const int*)d_in[11];
    const int*   batc = (const int*)d_in[12];
    float* out = (float*)d_out;

    __half *pH;
    float *pA1, *pA2, *pA3;
    cudaGetSymbolAddress((void**)&pH,  g_Hh);
    cudaGetSymbolAddress((void**)&pA1, g_A1);
    cudaGetSymbolAddress((void**)&pA2, g_A2);
    cudaGetSymbolAddress((void**)&pA3, g_A3);

    const int NB = (NN + 255) / 256;          // 391
    const int EB = (NE + 255) / 256;          // 12500
    const int GB = (NN + 127) / 128;          // 782 gemm blocks
    const int SB = (NN * 32 + 255) / 256;     // 12500 spmm blocks (warp/row)

    // CSR build (per call, deterministic work)
    k_zero<<<256, 256>>>();
    k_hist<<<EB, 256>>>(rows);
    k_scan1<<<NB, 256>>>();
    k_scan2<<<1, 512>>>(NB);
    k_scan3<<<NB, 256>>>();
    k_scatter<<<EB, 256>>>(rows, cols, vals);

    // layer 1
    k_gemm<IND><<<GB, 128>>>(X, W1, b1, pH);
    k_spmm<<<SB, 256>>>(pH, pA1);
    // layer 2
    k_gemm<HD><<<GB, 128>>>(pA1, W2, b2, pH);
    k_spmm<<<SB, 256>>>(pH, pA2);
    // layer 3
    k_gemm<HD><<<GB, 128>>>(pA2, W3, b3, pH);
    k_spmm<<<SB, 256>>>(pH, pA3);

    // pool + head
    k_pool<<<512, 256>>>(batc);
    k_final<<<1, 64>>>(Wo, bo, out);
}